// round 16
// baseline (speedup 1.0000x reference)
#include <cuda_runtime.h>
#include <cstdint>

// penalty = sum_{b,k} S[b,k] * || P[i_b] - P[j_{b,k}] ||_2
// P [500000,128] f32, i [4096] i32, j [4096,64] i32, S [4096,64] f32 -> scalar f32.
// R16: R15 (full-b units, cp.async ring) with GWIN 3->4 (16 rows in flight at
// fill, 12 steady-state) at 6 blocks/SM. Tests in-flight depth vs occupancy.

#define B_TOTAL 4096
#define K_NEIGH 64
#define D_DIM   128
#define WPB     4
#define KPU     64              // k's per unit (warp) — full b
#define NGS     (KPU / 4)       // 16 group-sets of 4 rows per unit
#define GWIN    4               // group-sets in flight (16 rows/warp at fill)
#define FULL    0xFFFFFFFFu

__global__ void zero_out_kernel(float* out) { *out = 0.0f; }

__device__ __forceinline__ void cp_async16(unsigned int smem_dst, const void* gptr) {
    asm volatile("cp.async.cg.shared.global [%0], [%1], 16;"
                 :: "r"(smem_dst), "l"(gptr) : "memory");
}
__device__ __forceinline__ void cp_commit() {
    asm volatile("cp.async.commit_group;" ::: "memory");
}
template <int N>
__device__ __forceinline__ void cp_wait() {
    asm volatile("cp.async.wait_group %0;" :: "n"(N) : "memory");
}

__global__ __launch_bounds__(WPB * 32, 6)
void custom_loss_kernel(const float* __restrict__ P,
                        const int*   __restrict__ i_idx,
                        const int*   __restrict__ j_idx,
                        const float* __restrict__ S,
                        float* __restrict__ out) {
    const int lane = threadIdx.x & 31;
    const int w    = threadIdx.x >> 5;
    const int b    = blockIdx.x * WPB + w;          // one warp per b
    const int g    = lane >> 3;                     // row group (0..3)
    const int sub  = lane & 7;                      // lane within group

    __shared__ int    sJ[WPB][KPU];
    __shared__ float  sS[WPB][KPU];
    // Per-warp ring: GWIN slots x 4 rows x 512B (float4-indexed)
    __shared__ float4 buf[WPB][GWIN * 4 * 32];

    // Early global loads, then stage to smem (64 j's + 64 S's per warp).
    const unsigned irow = (unsigned)i_idx[b];
    const int   jv0 = j_idx[b * K_NEIGH + lane];
    const int   jv1 = j_idx[b * K_NEIGH + 32 + lane];
    const float sv0 = S[b * K_NEIGH + lane];
    const float sv1 = S[b * K_NEIGH + 32 + lane];

    // Pi stays in registers via LDG.
    const float4* PiRow = reinterpret_cast<const float4*>(P + irow * (unsigned)D_DIM);
    float4 pi4[4];
    #pragma unroll
    for (int it = 0; it < 4; it++)
        pi4[it] = __ldg(PiRow + sub + 8 * it);

    sJ[w][lane]      = jv0;
    sJ[w][32 + lane] = jv1;
    sS[w][lane]      = sv0;
    sS[w][32 + lane] = sv1;
    __syncwarp();

    const unsigned int sbase =
        (unsigned int)__cvta_generic_to_shared(&buf[w][0]);
    const unsigned int laneoff = ((unsigned)g * 32 + (unsigned)sub) * 16u;

    // Prologue: fill GWIN group-sets via cp.async.
    #pragma unroll
    for (int q = 0; q < GWIN; q++) {
        unsigned jr = (unsigned)sJ[w][4 * q + g];
        const float* row = P + jr * (unsigned)D_DIM;
        #pragma unroll
        for (int it = 0; it < 4; it++)
            cp_async16(sbase + (unsigned)q * 2048u + laneoff + (unsigned)it * 128u,
                       row + it * 32 + sub * 4);
        cp_commit();
    }

    float acc = 0.0f;
    #pragma unroll
    for (int gs = 0; gs < NGS; gs++) {
        const int q = gs % GWIN;    // compile-time after full unroll

        // Wait until group-set gs has landed.
        if (gs == NGS - 1)       cp_wait<0>();
        else if (gs == NGS - 2)  cp_wait<1>();
        else if (gs == NGS - 3)  cp_wait<2>();
        else                     cp_wait<GWIN - 1>();

        // Consume: each lane reads back exactly the 4x16B it copied.
        float sq = 0.0f;
        #pragma unroll
        for (int it = 0; it < 4; it++) {
            const float4 pjv = buf[w][q * 128 + g * 32 + it * 8 + sub];
            float dx = pi4[it].x - pjv.x;
            float dy = pi4[it].y - pjv.y;
            float dz = pi4[it].z - pjv.z;
            float dw = pi4[it].w - pjv.w;
            sq += dx * dx + dy * dy + dz * dz + dw * dw;
        }

        // Refill slot q (keeps 12-16 rows in flight).
        if (gs + GWIN < NGS) {
            unsigned jr = (unsigned)sJ[w][4 * (gs + GWIN) + g];
            const float* row = P + jr * (unsigned)D_DIM;
            #pragma unroll
            for (int it = 0; it < 4; it++)
                cp_async16(sbase + (unsigned)q * 2048u + laneoff + (unsigned)it * 128u,
                           row + it * 32 + sub * 4);
            cp_commit();
        }

        // Reduce within each 8-lane group (4 rows per 3 shuffles).
        sq += __shfl_xor_sync(FULL, sq, 1);
        sq += __shfl_xor_sync(FULL, sq, 2);
        sq += __shfl_xor_sync(FULL, sq, 4);

        if (sub == 0)
            acc += sqrtf(sq) * sS[w][4 * gs + g];
    }

    // Lanes 0,8,16,24 hold partials; one atomic per warp.
    acc += __shfl_xor_sync(FULL, acc, 8);
    acc += __shfl_xor_sync(FULL, acc, 16);
    if (lane == 0) atomicAdd(out, acc);
}

extern "C" void kernel_launch(void* const* d_in, const int* in_sizes, int n_in,
                              void* d_out, int out_size) {
    const float* P  = (const float*)d_in[0];
    const int*   ii = (const int*)  d_in[1];
    const int*   jj = (const int*)  d_in[2];
    const float* S  = (const float*)d_in[3];
    float* out = (float*)d_out;

    zero_out_kernel<<<1, 1>>>(out);
    custom_loss_kernel<<<B_TOTAL / WPB, WPB * 32>>>(P, ii, jj, S, out);
}

// round 17
// speedup vs baseline: 1.1738x; 1.1738x over previous
#include <cuda_runtime.h>
#include <cstdint>

// penalty = sum_{b,k} S[b,k] * || P[i_b] - P[j_{b,k}] ||_2
// P [500000,128] f32, i [4096] i32, j [4096,64] i32, S [4096,64] f32 -> scalar f32.
// R17: R15 core (full-b units, GWIN=3 cp.async ring) with 64-thread blocks
// (grid 2048, ~14 blocks/SM -> finer single-wave load balance) and prologue
// gathers issued from shfl-broadcast register indices (no smem round-trip).

#define B_TOTAL 4096
#define K_NEIGH 64
#define D_DIM   128
#define WPB     2               // warps per block (64-thread blocks)
#define KPU     64              // k's per unit (warp) — full b
#define NGS     (KPU / 4)       // 16 group-sets of 4 rows per unit
#define GWIN    3               // group-sets in flight
#define FULL    0xFFFFFFFFu

__global__ void zero_out_kernel(float* out) { *out = 0.0f; }

__device__ __forceinline__ void cp_async16(unsigned int smem_dst, const void* gptr) {
    asm volatile("cp.async.cg.shared.global [%0], [%1], 16;"
                 :: "r"(smem_dst), "l"(gptr) : "memory");
}
__device__ __forceinline__ void cp_commit() {
    asm volatile("cp.async.commit_group;" ::: "memory");
}
template <int N>
__device__ __forceinline__ void cp_wait() {
    asm volatile("cp.async.wait_group %0;" :: "n"(N) : "memory");
}

__global__ __launch_bounds__(WPB * 32, 14)
void custom_loss_kernel(const float* __restrict__ P,
                        const int*   __restrict__ i_idx,
                        const int*   __restrict__ j_idx,
                        const float* __restrict__ S,
                        float* __restrict__ out) {
    const int lane = threadIdx.x & 31;
    const int w    = threadIdx.x >> 5;
    const int b    = blockIdx.x * WPB + w;          // one warp per b
    const int g    = lane >> 3;                     // row group (0..3)
    const int sub  = lane & 7;                      // lane within group

    __shared__ int    sJ[WPB][KPU];
    __shared__ float  sS[WPB][KPU];
    // Per-warp ring: GWIN slots x 4 rows x 512B (float4-indexed)
    __shared__ float4 buf[WPB][GWIN * 4 * 32];

    // Early global loads.
    const unsigned irow = (unsigned)i_idx[b];
    const int   jv0 = j_idx[b * K_NEIGH + lane];
    const int   jv1 = j_idx[b * K_NEIGH + 32 + lane];
    const float sv0 = S[b * K_NEIGH + lane];
    const float sv1 = S[b * K_NEIGH + 32 + lane];

    const unsigned int sbase =
        (unsigned int)__cvta_generic_to_shared(&buf[w][0]);
    const unsigned int laneoff = ((unsigned)g * 32 + (unsigned)sub) * 16u;

    // Prologue: fill GWIN group-sets straight from register indices
    // (shfl broadcast; rows 0..11 all live in jv0) — no smem dependency.
    #pragma unroll
    for (int q = 0; q < GWIN; q++) {
        unsigned jr = (unsigned)__shfl_sync(FULL, jv0, 4 * q + g);
        const float* row = P + jr * (unsigned)D_DIM;
        #pragma unroll
        for (int it = 0; it < 4; it++)
            cp_async16(sbase + (unsigned)q * 2048u + laneoff + (unsigned)it * 128u,
                       row + it * 32 + sub * 4);
        cp_commit();
    }

    // Pi stays in registers via LDG (overlaps with prologue fills).
    const float4* PiRow = reinterpret_cast<const float4*>(P + irow * (unsigned)D_DIM);
    float4 pi4[4];
    #pragma unroll
    for (int it = 0; it < 4; it++)
        pi4[it] = __ldg(PiRow + sub + 8 * it);

    // Stage indices/scales to smem for the steady-state refills.
    sJ[w][lane]      = jv0;
    sJ[w][32 + lane] = jv1;
    sS[w][lane]      = sv0;
    sS[w][32 + lane] = sv1;
    __syncwarp();

    float acc = 0.0f;
    #pragma unroll
    for (int gs = 0; gs < NGS; gs++) {
        const int q = gs % GWIN;    // compile-time after full unroll

        // Wait until group-set gs has landed.
        if (gs == NGS - 1)       cp_wait<0>();
        else if (gs == NGS - 2)  cp_wait<1>();
        else                     cp_wait<GWIN - 1>();

        // Consume: each lane reads back exactly the 4x16B it copied.
        float sq = 0.0f;
        #pragma unroll
        for (int it = 0; it < 4; it++) {
            const float4 pjv = buf[w][q * 128 + g * 32 + it * 8 + sub];
            float dx = pi4[it].x - pjv.x;
            float dy = pi4[it].y - pjv.y;
            float dz = pi4[it].z - pjv.z;
            float dw = pi4[it].w - pjv.w;
            sq += dx * dx + dy * dy + dz * dz + dw * dw;
        }

        // Refill slot q (keeps ~8-12 rows in flight).
        if (gs + GWIN < NGS) {
            unsigned jr = (unsigned)sJ[w][4 * (gs + GWIN) + g];
            const float* row = P + jr * (unsigned)D_DIM;
            #pragma unroll
            for (int it = 0; it < 4; it++)
                cp_async16(sbase + (unsigned)q * 2048u + laneoff + (unsigned)it * 128u,
                           row + it * 32 + sub * 4);
            cp_commit();
        }

        // Reduce within each 8-lane group (4 rows per 3 shuffles).
        sq += __shfl_xor_sync(FULL, sq, 1);
        sq += __shfl_xor_sync(FULL, sq, 2);
        sq += __shfl_xor_sync(FULL, sq, 4);

        if (sub == 0)
            acc += sqrtf(sq) * sS[w][4 * gs + g];
    }

    // Lanes 0,8,16,24 hold partials; one atomic per warp.
    acc += __shfl_xor_sync(FULL, acc, 8);
    acc += __shfl_xor_sync(FULL, acc, 16);
    if (lane == 0) atomicAdd(out, acc);
}

extern "C" void kernel_launch(void* const* d_in, const int* in_sizes, int n_in,
                              void* d_out, int out_size) {
    const float* P  = (const float*)d_in[0];
    const int*   ii = (const int*)  d_in[1];
    const int*   jj = (const int*)  d_in[2];
    const float* S  = (const float*)d_in[3];
    float* out = (float*)d_out;

    zero_out_kernel<<<1, 1>>>(out);
    custom_loss_kernel<<<B_TOTAL / WPB, WPB * 32>>>(P, ii, jj, S, out);
}